// round 13
// baseline (speedup 1.0000x reference)
#include <cuda_runtime.h>
#include <cuda_bf16.h>
#include <cuda_fp16.h>
#include <cstdint>

#define NMAX 100000
#define EMAX 3200000
#define C 256

__device__ uint16_t g_H8[(size_t)NMAX * 128];  // GEMM1 output (fp8 e4m3 pairs), 256B/row
__device__ __half g_AGG16[(size_t)NMAX * C];   // agg output (fp16, GEMM2 input)
__device__ float g_dotp[(size_t)NMAX * 4];     // fused final partial dots
__device__ int   g_deg[NMAX];
__device__ float g_dinv[NMAX];
__device__ int   g_off[NMAX + 1];
__device__ int   g_cursor[NMAX];
__device__ int   g_src[EMAX];
__device__ int   g_bsum[128];
__device__ int   g_bpre[128];
__device__ int   g_idx64;

// bf16 transposed+swizzled weight images
__device__ uint32_t g_W0[2 * 16384];
__device__ uint32_t g_W1[2 * 16384];

// ---------------------------------------------------------------------------
// helpers
// ---------------------------------------------------------------------------
__device__ __forceinline__ uint32_t smem_u32(const void* p) {
    uint32_t a;
    asm("{ .reg .u64 t; cvta.to.shared.u64 t, %1; cvt.u32.u64 %0, t; }" : "=r"(a) : "l"(p));
    return a;
}
__device__ __forceinline__ void ldsm_x4(uint32_t* r, uint32_t addr) {
    asm volatile("ldmatrix.sync.aligned.m8n8.x4.shared.b16 {%0,%1,%2,%3}, [%4];"
                 : "=r"(r[0]), "=r"(r[1]), "=r"(r[2]), "=r"(r[3]) : "r"(addr));
}
__device__ __forceinline__ void ldsm_x4_t(uint32_t* r, uint32_t addr) {
    asm volatile("ldmatrix.sync.aligned.m8n8.x4.trans.shared.b16 {%0,%1,%2,%3}, [%4];"
                 : "=r"(r[0]), "=r"(r[1]), "=r"(r[2]), "=r"(r[3]) : "r"(addr));
}
__device__ __forceinline__ void mma_bf16(float* d, const uint32_t* a, const uint32_t* b) {
    asm volatile(
        "mma.sync.aligned.m16n8k16.row.col.f32.bf16.bf16.f32 "
        "{%0,%1,%2,%3}, {%4,%5,%6,%7}, {%8,%9}, {%0,%1,%2,%3};"
        : "+f"(d[0]), "+f"(d[1]), "+f"(d[2]), "+f"(d[3])
        : "r"(a[0]), "r"(a[1]), "r"(a[2]), "r"(a[3]), "r"(b[0]), "r"(b[1]));
}
__device__ __forceinline__ uint32_t pack_bf16(float a, float b) {
    uint32_t r;
    asm("cvt.rn.bf16x2.f32 %0, %1, %2;" : "=r"(r) : "f"(b), "f"(a));
    return r;
}
__device__ __forceinline__ uint16_t pack_fp8x2(float a, float b) {
    uint16_t r;
    asm("cvt.rn.satfinite.e4m3x2.f32 %0, %1, %2;" : "=h"(r) : "f"(b), "f"(a));
    return r;
}
__device__ __forceinline__ __half2 fp8x2_to_h2(uint16_t v) {
    uint32_t w;
    asm("cvt.rn.f16x2.e4m3x2 %0, %1;" : "=r"(w) : "h"(v));
    return *(__half2*)&w;
}

// ---------------------------------------------------------------------------
// init: zero degrees + edge dtype detect (block 0)
// ---------------------------------------------------------------------------
__global__ void init_kernel(const void* ei, long E, int M) {
    int i = blockIdx.x * blockDim.x + threadIdx.x;
    if (i < M) g_deg[i] = 0;
    if (blockIdx.x == 0) {
        const int* w = (const int*)ei;
        int tid = threadIdx.x;
        int any = 0;
        long n = E < 2048 ? E : 2048;
        for (long k = tid; k < n; k += blockDim.x)
            if (w[2 * k + 1] != 0) any = 1;
        any = __syncthreads_or(any);
        if (tid == 0) g_idx64 = any ? 0 : 1;
    }
}
__device__ __forceinline__ long fetch_idx(const void* ei, long pos) {
    if (g_idx64) return (long)((const long long*)ei)[pos];
    return (long)((const int*)ei)[pos];
}

// ---------------------------------------------------------------------------
// degree / CSR build
// ---------------------------------------------------------------------------
__global__ void count_deg(const void* ei, long E) {
    long e = (long)blockIdx.x * blockDim.x + threadIdx.x;
    if (e < E) atomicAdd(&g_deg[fetch_idx(ei, E + e)], 1);
}
// scan phase1 also computes dinv (fused; deg is final here)
__global__ void scan_phase1(int M) {
    __shared__ int s[1024];
    int tid = threadIdx.x;
    int i = blockIdx.x * 1024 + tid;
    int v = (i < M) ? g_deg[i] : 0;
    s[tid] = v;
    if (i < M) g_dinv[i] = rsqrtf((float)(v + 1));  // +1 self loop
    __syncthreads();
    for (int d = 512; d > 0; d >>= 1) {
        if (tid < d) s[tid] += s[tid + d];
        __syncthreads();
    }
    if (tid == 0) g_bsum[blockIdx.x] = s[0];
}
__global__ void scan_phase2(int nb, int M, int Etot) {
    __shared__ int s[128];
    int tid = threadIdx.x;
    int v = (tid < nb) ? g_bsum[tid] : 0;
    s[tid] = v;
    __syncthreads();
    for (int d = 1; d < 128; d <<= 1) {
        int t = (tid >= d) ? s[tid - d] : 0;
        __syncthreads();
        s[tid] += t;
        __syncthreads();
    }
    if (tid < nb) g_bpre[tid] = s[tid] - v;
    if (tid == 0) g_off[M] = Etot;
}
__global__ void scan_phase3(int M) {
    __shared__ int s[1024];
    int tid = threadIdx.x;
    int i = blockIdx.x * 1024 + tid;
    int v = (i < M) ? g_deg[i] : 0;
    s[tid] = v;
    __syncthreads();
    for (int d = 1; d < 1024; d <<= 1) {
        int t = (tid >= d) ? s[tid - d] : 0;
        __syncthreads();
        s[tid] += t;
        __syncthreads();
    }
    if (i < M) {
        int excl = s[tid] - v + g_bpre[blockIdx.x];
        g_off[i] = excl;
        g_cursor[i] = excl;
    }
}
__global__ void fill_csr(const void* ei, long E) {
    long e = (long)blockIdx.x * blockDim.x + threadIdx.x;
    if (e < E) {
        int row = (int)fetch_idx(ei, e);
        int col = (int)fetch_idx(ei, E + e);
        g_src[atomicAdd(&g_cursor[col], 1)] = row;
    }
}

// ---------------------------------------------------------------------------
// CSR aggregation fp8 -> fp16 (HFMA2). One warp per node, range [n0, n1).
// ---------------------------------------------------------------------------
__device__ __forceinline__ void q8h_fma(uint2 v, __half2 nm, __half2* acc) {
    acc[0] = __hfma2(fp8x2_to_h2((uint16_t)(v.x & 0xFFFF)), nm, acc[0]);
    acc[1] = __hfma2(fp8x2_to_h2((uint16_t)(v.x >> 16)),    nm, acc[1]);
    acc[2] = __hfma2(fp8x2_to_h2((uint16_t)(v.y & 0xFFFF)), nm, acc[2]);
    acc[3] = __hfma2(fp8x2_to_h2((uint16_t)(v.y >> 16)),    nm, acc[3]);
}

__global__ void __launch_bounds__(256, 8) agg_kernel(int n0, int n1) {
    long gt = (long)blockIdx.x * blockDim.x + threadIdx.x;
    int n = n0 + (int)(gt >> 5);
    int lane = (int)(gt & 31);
    if (n >= n1) return;

    const uint2* H8 = (const uint2*)g_H8;
    float dn = g_dinv[n];
    __half2 acc[4];
    acc[0] = acc[1] = acc[2] = acc[3] = __float2half2_rn(0.f);

    q8h_fma(__ldg(H8 + (long)n * 32 + lane), __float2half2_rn(dn * dn), acc);

    int i = g_off[n];
    int end = g_off[n + 1];

    for (; i + 3 < end; i += 4) {
        int r0 = __ldg(g_src + i + 0);
        int r1 = __ldg(g_src + i + 1);
        int r2 = __ldg(g_src + i + 2);
        int r3 = __ldg(g_src + i + 3);
        __half2 nm0 = __float2half2_rn(dn * __ldg(g_dinv + r0));
        __half2 nm1 = __float2half2_rn(dn * __ldg(g_dinv + r1));
        __half2 nm2 = __float2half2_rn(dn * __ldg(g_dinv + r2));
        __half2 nm3 = __float2half2_rn(dn * __ldg(g_dinv + r3));
        uint2 v0 = __ldg(H8 + (long)r0 * 32 + lane);
        uint2 v1 = __ldg(H8 + (long)r1 * 32 + lane);
        uint2 v2 = __ldg(H8 + (long)r2 * 32 + lane);
        uint2 v3 = __ldg(H8 + (long)r3 * 32 + lane);
        q8h_fma(v0, nm0, acc);
        q8h_fma(v1, nm1, acc);
        q8h_fma(v2, nm2, acc);
        q8h_fma(v3, nm3, acc);
    }
    for (; i < end; i++) {
        int r0 = __ldg(g_src + i);
        q8h_fma(__ldg(H8 + (long)r0 * 32 + lane),
                __float2half2_rn(dn * __ldg(g_dinv + r0)), acc);
    }

    uint4 o;
    o.x = *(uint32_t*)&acc[0];
    o.y = *(uint32_t*)&acc[1];
    o.z = *(uint32_t*)&acc[2];
    o.w = *(uint32_t*)&acc[3];
    ((uint4*)g_AGG16)[(long)n * 32 + lane] = o;
}

// ---------------------------------------------------------------------------
// Weight prep: both matrices in one launch
// ---------------------------------------------------------------------------
__global__ void prep_weights2(const float* __restrict__ Wa, const float* __restrict__ Wb,
                              uint32_t* __restrict__ img_a, uint32_t* __restrict__ img_b) {
    int idx = blockIdx.x * blockDim.x + threadIdx.x;
    const float* W = (idx < 32768) ? Wa : Wb;
    uint32_t* img = (idx < 32768) ? img_a : img_b;
    int li = idx & 32767;
    int tile = li >> 14;
    int k = (li >> 6) & 255;
    int np = li & 63;
    int n = np * 2;
    int gn = tile * 128 + n;
    float a = W[gn * 256 + k];
    float b = W[(gn + 1) * 256 + k];
    uint32_t boff = (uint32_t)k * 256 + ((((n >> 3) ^ (k & 7)) << 4) | ((n & 7) * 2));
    img[tile * 16384 + (boff >> 2)] = pack_bf16(a, b);
}

// ---------------------------------------------------------------------------
// HMMA GEMM, single-pass bf16, persistent over tile range [t0, t1).
// ---------------------------------------------------------------------------
#define SM_B 0
#define SM_A 65536
#define SM_TOT 81920

template <bool PRE, bool POST, bool IN16, bool OUT8, bool FUSED>
__global__ void __launch_bounds__(256, 1)
gemm_hmma(const void* __restrict__ Avoid,
          const uint32_t* __restrict__ img,
          const float* __restrict__ bpre, const float* __restrict__ bpost,
          uint16_t* __restrict__ Out8, const float* __restrict__ W2,
          float* __restrict__ dotp, int M, int t0, int t1) {
    extern __shared__ char smem[];
    const uint32_t sb = smem_u32(smem);
    const int tid = threadIdx.x;
    const int lane = tid & 31;
    const int wid = tid >> 5;
    const int wm = wid & 3;
    const int wn = wid >> 2;
    const int n0 = blockIdx.y * 128;

    const float* Af = (const float*)Avoid;
    const __half* Ah16 = (const __half*)Avoid;

    // ---- copy B image ----
    {
        const uint4* sh = (const uint4*)(img + blockIdx.y * 16384);
        uint4* dh = (uint4*)(smem + SM_B);
#pragma unroll
        for (int i = 0; i < 16; i++)
            dh[tid + i * 256] = sh[tid + i * 256];
    }

    const int frow = tid >> 1;
    const int fkh = (tid & 1) * 32;

    float4 pf[8];
    uint4 pf16[4];
    int t = t0 + blockIdx.x;
    {
        bool ok = (t < t1) && (t * 128 + frow < M);
        if (IN16) {
            const uint4* Ab = (const uint4*)(Ah16 + (long)(t * 128 + frow) * 256 + fkh);
#pragma unroll
            for (int j = 0; j < 4; j++)
                pf16[j] = ok ? Ab[j] : make_uint4(0, 0, 0, 0);
        } else {
            const float* Ab = Af + (long)(t * 128 + frow) * 256 + fkh;
#pragma unroll
            for (int j = 0; j < 8; j++)
                pf[j] = ok ? *(const float4*)(Ab + j * 4) : make_float4(0.f, 0.f, 0.f, 0.f);
        }
    }

    const int g = lane >> 3;

    for (; t < t1; t += 74) {
        const int m0 = t * 128;
        float acc[2][8][4];
#pragma unroll
        for (int a_ = 0; a_ < 2; a_++)
#pragma unroll
            for (int b_ = 0; b_ < 8; b_++)
#pragma unroll
                for (int c_ = 0; c_ < 4; c_++) acc[a_][b_][c_] = 0.f;

        for (int ch = 0; ch < 4; ch++) {
            // ---- convert prefetched chunk -> A smem (bf16, swizzled) ----
            {
                uint32_t base_a = sb + SM_A + frow * 128;
                if (IN16) {
#pragma unroll
                    for (int j = 0; j < 4; j++) {
                        uint4 q = pf16[j];
                        float2 f0 = __half22float2(*(const __half2*)&q.x);
                        float2 f1 = __half22float2(*(const __half2*)&q.y);
                        float2 f2 = __half22float2(*(const __half2*)&q.z);
                        float2 f3 = __half22float2(*(const __half2*)&q.w);
                        if (PRE) {
                            const float4 b0 = *(const float4*)(bpre + ch * 64 + fkh + j * 8);
                            const float4 b1 = *(const float4*)(bpre + ch * 64 + fkh + j * 8 + 4);
                            f0.x = fmaxf(f0.x + b0.x, 0.f); f0.y = fmaxf(f0.y + b0.y, 0.f);
                            f1.x = fmaxf(f1.x + b0.z, 0.f); f1.y = fmaxf(f1.y + b0.w, 0.f);
                            f2.x = fmaxf(f2.x + b1.x, 0.f); f2.y = fmaxf(f2.y + b1.y, 0.f);
                            f3.x = fmaxf(f3.x + b1.z, 0.f); f3.y = fmaxf(f3.y + b1.w, 0.f);
                        }
                        uint32_t h0 = pack_bf16(f0.x, f0.y);
                        uint32_t h1 = pack_bf16(f1.x, f1.y);
                        uint32_t h2 = pack_bf16(f2.x, f2.y);
                        uint32_t h3 = pack_bf16(f3.x, f3.y);
                        int kk = fkh + j * 8;
                        uint32_t off0 = ((((kk >> 3) ^ (frow & 7)) << 4));
                        asm volatile("st.shared.v2.b32 [%0], {%1, %2};"
                                     :: "r"(base_a + off0), "r"(h0), "r"(h1) : "memory");
                        asm volatile("st.shared.v2.b32 [%0], {%1, %2};"
                                     :: "r"(base_a + off0 + 8), "r"(h2), "r"(h3) : "memory");
                    }
                } else {
#pragma unroll
                    for (int j = 0; j < 8; j++) {
                        float4 v = pf[j];
                        if (PRE) {
                            const float4 bb = *(const float4*)(bpre + ch * 64 + fkh + j * 4);
                            v.x = fmaxf(v.x + bb.x, 0.f);
                            v.y = fmaxf(v.y + bb.y, 0.f);
                            v.z = fmaxf(v.z + bb.z, 0.f);
                            v.w = fmaxf(v.w + bb.w, 0.f);
                        }
                        uint32_t h0 = pack_bf16(v.x, v.y);
                        uint32_t h1 = pack_bf16(v.z, v.w);
                        int kk = fkh + j * 4;
                        uint32_t off = ((((kk >> 3) ^ (frow & 7)) << 4) | ((kk & 7) * 2));
                        asm volatile("st.shared.v2.b32 [%0], {%1, %2};"
                                     :: "r"(base_a + off), "r"(h0), "r"(h1) : "memory");
                    }
                }
            }
            __syncthreads();

            // ---- prefetch next chunk ----
            {
                int nc = ch + 1;
                int nt = t;
                if (nc == 4) { nc = 0; nt = t + 74; }
                if (nt < t1) {
                    bool ok = (nt * 128 + frow) < M;
                    if (IN16) {
                        const uint4* Ab = (const uint4*)(Ah16 + (long)(nt * 128 + frow) * 256 + nc * 64 + fkh);
#pragma unroll
                        for (int j = 0; j < 4; j++)
                            pf16[j] = ok ? Ab[j] : make_uint4(0, 0, 0, 0);
                    } else {
                        const float* Ab = Af + (long)(nt * 128 + frow) * 256 + nc * 64 + fkh;
#pragma unroll
                        for (int j = 0; j < 8; j++)
                            pf[j] = ok ? *(const float4*)(Ab + j * 4) : make_float4(0.f, 0.f, 0.f, 0.f);
                    }
                }
            }

            // ---- MMA over 4 k16 steps ----
#pragma unroll
            for (int ks = 0; ks < 4; ks++) {
                const int klocal = ks * 16;
                const int kglob = ch * 64 + klocal;

                uint32_t ah[2][4];
#pragma unroll
                for (int mf = 0; mf < 2; mf++) {
                    int m = wm * 32 + mf * 16 + ((g & 1) << 3) + (lane & 7);
                    int kc = klocal + ((g >> 1) << 3);
                    uint32_t off = (uint32_t)m * 128 + ((((kc >> 3) ^ (m & 7)) << 4));
                    ldsm_x4(ah[mf], sb + SM_A + off);
                }

                uint32_t bh[8][2];
#pragma unroll
                for (int q = 0; q < 4; q++) {
                    int nb = wn * 64 + q * 16 + ((g >> 1) << 3);
                    int kr = kglob + ((g & 1) << 3) + (lane & 7);
                    uint32_t off = (uint32_t)kr * 256 + ((((nb >> 3) ^ (kr & 7)) << 4));
                    uint32_t r[4];
                    ldsm_x4_t(r, sb + SM_B + off);
                    bh[q * 2][0] = r[0]; bh[q * 2][1] = r[1];
                    bh[q * 2 + 1][0] = r[2]; bh[q * 2 + 1][1] = r[3];
                }

#pragma unroll
                for (int mf = 0; mf < 2; mf++)
#pragma unroll
                    for (int nf = 0; nf < 8; nf++)
                        mma_bf16(acc[mf][nf], ah[mf], bh[nf]);
            }
            __syncthreads();
        }

        // ---- epilogue ----
#pragma unroll
        for (int mf = 0; mf < 2; mf++) {
#pragma unroll
            for (int half = 0; half < 2; half++) {
                int m = m0 + wm * 32 + mf * 16 + (lane >> 2) + half * 8;
                float dot = 0.f;
#pragma unroll
                for (int nf = 0; nf < 8; nf++) {
                    float2 v;
                    v.x = acc[mf][nf][half * 2];
                    v.y = acc[mf][nf][half * 2 + 1];
                    if (POST) {
                        const float2 bb = *(const float2*)(bpost + n0 + wn * 64 + nf * 8 + 2 * (lane & 3));
                        v.x = fmaxf(v.x + bb.x, 0.f);
                        v.y = fmaxf(v.y + bb.y, 0.f);
                    }
                    if (FUSED) {
                        const float2 w2v = *(const float2*)(W2 + n0 + wn * 64 + nf * 8 + 2 * (lane & 3));
                        dot = fmaf(v.x, w2v.x, dot);
                        dot = fmaf(v.y, w2v.y, dot);
                    } else if (OUT8) {
                        if (m < M) {
                            int col = n0 + wn * 64 + nf * 8 + 2 * (lane & 3);
                            Out8[(long)m * 128 + (col >> 1)] = pack_fp8x2(v.x, v.y);
                        }
                    }
                }
                if (FUSED) {
                    dot += __shfl_xor_sync(0xFFFFFFFFu, dot, 1);
                    dot += __shfl_xor_sync(0xFFFFFFFFu, dot, 2);
                    if ((lane & 3) == 0 && m < M)
                        dotp[(long)m * 4 + blockIdx.y * 2 + wn] = dot;
                }
            }
        }
    }
}

// ---------------------------------------------------------------------------
// Final combine
// ---------------------------------------------------------------------------
__global__ void final_combine(const float* __restrict__ b2, float* __restrict__ out, int M) {
    int m = blockIdx.x * blockDim.x + threadIdx.x;
    if (m < M) {
        float4 p = ((const float4*)g_dotp)[m];
        float v = fmaxf(p.x + p.y + p.z + p.w + b2[0], 0.f);
        out[m] = 1.f / (1.f + __expf(-v));
    }
}

// ---------------------------------------------------------------------------
extern "C" void kernel_launch(void* const* d_in, const int* in_sizes, int n_in,
                              void* d_out, int out_size) {
    const float* x     = (const float*)d_in[0];
    const void*  ei    = d_in[1];
    const float* W_gcn = (const float*)d_in[2];
    const float* b_gcn = (const float*)d_in[3];
    const float* W1    = (const float*)d_in[4];
    const float* b1    = (const float*)d_in[5];
    const float* W2    = (const float*)d_in[6];
    const float* b2    = (const float*)d_in[7];
    float* out = (float*)d_out;

    const int  M = in_sizes[0] / C;
    const long E = (long)in_sizes[1] / 2;
    const int ntiles = (M + 127) / 128;

    uint16_t* H8;
    __half* AGG16;
    float* dotp;
    cudaGetSymbolAddress((void**)&H8, g_H8);
    cudaGetSymbolAddress((void**)&AGG16, g_AGG16);
    cudaGetSymbolAddress((void**)&dotp, g_dotp);
    uint32_t *W0, *W1i;
    cudaGetSymbolAddress((void**)&W0, g_W0);
    cudaGetSymbolAddress((void**)&W1i, g_W1);

    static cudaStream_t s1 = nullptr;
    static cudaEvent_t evFork = nullptr, evJoin = nullptr;
    static cudaEvent_t evAgg0 = nullptr, evAgg1 = nullptr, evG2 = nullptr;
    if (!s1) {
        cudaStreamCreateWithFlags(&s1, cudaStreamNonBlocking);
        cudaEventCreateWithFlags(&evFork, cudaEventDisableTiming);
        cudaEventCreateWithFlags(&evJoin, cudaEventDisableTiming);
        cudaEventCreateWithFlags(&evAgg0, cudaEventDisableTiming);
        cudaEventCreateWithFlags(&evAgg1, cudaEventDisableTiming);
        cudaEventCreateWithFlags(&evG2, cudaEventDisableTiming);
        cudaFuncSetAttribute(gemm_hmma<false, false, false, true, false>,
                             cudaFuncAttributeMaxDynamicSharedMemorySize, SM_TOT);
        cudaFuncSetAttribute(gemm_hmma<true, true, true, false, true>,
                             cudaFuncAttributeMaxDynamicSharedMemorySize, SM_TOT);
    }

    // ---- fork: stream 0 = CSR chain, s1 = weights + GEMM1 ----
    cudaEventRecord(evFork, 0);
    cudaStreamWaitEvent(s1, evFork, 0);

    // chain A (stream 0): init(detect+zero) -> count -> scan(+dinv) -> fill
    init_kernel<<<(M + 255) / 256, 256>>>(ei, E, M);
    count_deg<<<(int)((E + 255) / 256), 256>>>(ei, E);
    int nb = (M + 1023) / 1024;
    scan_phase1<<<nb, 1024>>>(M);
    scan_phase2<<<1, 128>>>(nb, M, (int)E);
    scan_phase3<<<nb, 1024>>>(M);
    fill_csr<<<(int)((E + 255) / 256), 256>>>(ei, E);

    // chain B (s1): weight prep (both) + GEMM1 (H8 = fp8(x @ W_gcn^T))
    prep_weights2<<<256, 256, 0, s1>>>(W_gcn, W1, W0, W1i);
    dim3 ggrid(74, 2);
    gemm_hmma<false, false, false, true, false><<<ggrid, 256, SM_TOT, s1>>>(
        x, W0, nullptr, nullptr, H8, nullptr, nullptr, M, 0, ntiles);

    // ---- join ----
    cudaEventRecord(evJoin, s1);
    cudaStreamWaitEvent(0, evJoin, 0);

    // ---- 2-chunk pipelined agg (stream 0) / GEMM2 (s1) ----
    const int tHalf = (ntiles + 1) / 2;
    int nSplit = tHalf * 128;
    if (nSplit > M) nSplit = M;

    // agg chunk 0
    {
        long tcount = (long)nSplit * 32;
        agg_kernel<<<(int)((tcount + 255) / 256), 256>>>(0, nSplit);
        cudaEventRecord(evAgg0, 0);
    }
    // GEMM2 chunk 0 on s1 (hides under agg chunk 1)
    cudaStreamWaitEvent(s1, evAgg0, 0);
    gemm_hmma<true, true, true, false, true><<<ggrid, 256, SM_TOT, s1>>>(
        AGG16, W1i, b_gcn, b1, nullptr, W2, dotp, M, 0, tHalf);

    // agg chunk 1
    if (nSplit < M) {
        long tcount = (long)(M - nSplit) * 32;
        agg_kernel<<<(int)((tcount + 255) / 256), 256>>>(nSplit, M);
    }
    cudaEventRecord(evAgg1, 0);
    cudaStreamWaitEvent(s1, evAgg1, 0);
    if (tHalf < ntiles) {
        gemm_hmma<true, true, true, false, true><<<ggrid, 256, SM_TOT, s1>>>(
            AGG16, W1i, b_gcn, b1, nullptr, W2, dotp, M, tHalf, ntiles);
    }

    // ---- join GEMM2, combine ----
    cudaEventRecord(evG2, s1);
    cudaStreamWaitEvent(0, evG2, 0);
    final_combine<<<(M + 255) / 256, 256>>>(b2, out, M);
}

// round 14
// speedup vs baseline: 1.0266x; 1.0266x over previous
#include <cuda_runtime.h>
#include <cuda_bf16.h>
#include <cuda_fp16.h>
#include <cstdint>

#define NMAX 100000
#define EMAX 3200000
#define C 256

__device__ uint16_t g_H8[(size_t)NMAX * 128];  // GEMM1 output (fp8 e4m3 pairs), 256B/row
__device__ __half g_AGG16[(size_t)NMAX * C];   // agg output (fp16, GEMM2 input)
__device__ float g_dotp[(size_t)NMAX * 4];     // fused final partial dots
__device__ int   g_deg[NMAX];
__device__ float g_dinv[NMAX];
__device__ int   g_off[NMAX + 1];
__device__ int   g_cursor[NMAX];
__device__ int   g_src[EMAX];
__device__ int   g_bsum[128];
__device__ int   g_idx64;

// bf16 transposed+swizzled weight images
__device__ uint32_t g_W0[2 * 16384];
__device__ uint32_t g_W1[2 * 16384];

// ---------------------------------------------------------------------------
// helpers
// ---------------------------------------------------------------------------
__device__ __forceinline__ uint32_t smem_u32(const void* p) {
    uint32_t a;
    asm("{ .reg .u64 t; cvta.to.shared.u64 t, %1; cvt.u32.u64 %0, t; }" : "=r"(a) : "l"(p));
    return a;
}
__device__ __forceinline__ void ldsm_x4(uint32_t* r, uint32_t addr) {
    asm volatile("ldmatrix.sync.aligned.m8n8.x4.shared.b16 {%0,%1,%2,%3}, [%4];"
                 : "=r"(r[0]), "=r"(r[1]), "=r"(r[2]), "=r"(r[3]) : "r"(addr));
}
__device__ __forceinline__ void ldsm_x4_t(uint32_t* r, uint32_t addr) {
    asm volatile("ldmatrix.sync.aligned.m8n8.x4.trans.shared.b16 {%0,%1,%2,%3}, [%4];"
                 : "=r"(r[0]), "=r"(r[1]), "=r"(r[2]), "=r"(r[3]) : "r"(addr));
}
__device__ __forceinline__ void mma_bf16(float* d, const uint32_t* a, const uint32_t* b) {
    asm volatile(
        "mma.sync.aligned.m16n8k16.row.col.f32.bf16.bf16.f32 "
        "{%0,%1,%2,%3}, {%4,%5,%6,%7}, {%8,%9}, {%0,%1,%2,%3};"
        : "+f"(d[0]), "+f"(d[1]), "+f"(d[2]), "+f"(d[3])
        : "r"(a[0]), "r"(a[1]), "r"(a[2]), "r"(a[3]), "r"(b[0]), "r"(b[1]));
}
__device__ __forceinline__ uint32_t pack_bf16(float a, float b) {
    uint32_t r;
    asm("cvt.rn.bf16x2.f32 %0, %1, %2;" : "=r"(r) : "f"(b), "f"(a));
    return r;
}
__device__ __forceinline__ uint16_t pack_fp8x2(float a, float b) {
    uint16_t r;
    asm("cvt.rn.satfinite.e4m3x2.f32 %0, %1, %2;" : "=h"(r) : "f"(b), "f"(a));
    return r;
}
__device__ __forceinline__ __half2 fp8x2_to_h2(uint16_t v) {
    uint32_t w;
    asm("cvt.rn.f16x2.e4m3x2 %0, %1;" : "=r"(w) : "h"(v));
    return *(__half2*)&w;
}

// ---------------------------------------------------------------------------
// init: zero degrees + edge dtype detect (block 0)
// ---------------------------------------------------------------------------
__global__ void init_kernel(const void* ei, long E, int M) {
    int i = blockIdx.x * blockDim.x + threadIdx.x;
    if (i < M) g_deg[i] = 0;
    if (blockIdx.x == 0) {
        const int* w = (const int*)ei;
        int tid = threadIdx.x;
        int any = 0;
        long n = E < 2048 ? E : 2048;
        for (long k = tid; k < n; k += blockDim.x)
            if (w[2 * k + 1] != 0) any = 1;
        any = __syncthreads_or(any);
        if (tid == 0) g_idx64 = any ? 0 : 1;
    }
}
__device__ __forceinline__ long fetch_idx(const void* ei, long pos) {
    if (g_idx64) return (long)((const long long*)ei)[pos];
    return (long)((const int*)ei)[pos];
}

// ---------------------------------------------------------------------------
// degree / CSR build
// ---------------------------------------------------------------------------
__global__ void count_deg(const void* ei, long E) {
    long e = (long)blockIdx.x * blockDim.x + threadIdx.x;
    if (e < E) atomicAdd(&g_deg[fetch_idx(ei, E + e)], 1);
}
// scan phase1: block-sums of deg + dinv (deg is final here)
__global__ void scan_phase1(int M) {
    __shared__ int s[1024];
    int tid = threadIdx.x;
    int i = blockIdx.x * 1024 + tid;
    int v = (i < M) ? g_deg[i] : 0;
    s[tid] = v;
    if (i < M) g_dinv[i] = rsqrtf((float)(v + 1));  // +1 self loop
    __syncthreads();
    for (int d = 512; d > 0; d >>= 1) {
        if (tid < d) s[tid] += s[tid + d];
        __syncthreads();
    }
    if (tid == 0) g_bsum[blockIdx.x] = s[0];
}
// scan phase3 (phase2 merged): block prefix computed from g_bsum locally
__global__ void scan_phase3(int M) {
    __shared__ int s[1024];
    __shared__ int s2[128];
    int tid = threadIdx.x;
    int i = blockIdx.x * 1024 + tid;
    int v = (i < M) ? g_deg[i] : 0;
    s[tid] = v;
    // block prefix: sum of g_bsum[0 .. blockIdx.x)
    if (tid < 128)
        s2[tid] = (tid < blockIdx.x) ? g_bsum[tid] : 0;
    __syncthreads();
    // reduce s2 (128 -> 1) using first 64 threads
    for (int d = 64; d > 0; d >>= 1) {
        if (tid < d) s2[tid] += s2[tid + d];
        __syncthreads();
    }
    int bpre = s2[0];
    // inclusive scan of s
    for (int d = 1; d < 1024; d <<= 1) {
        int t = (tid >= d) ? s[tid - d] : 0;
        __syncthreads();
        s[tid] += t;
        __syncthreads();
    }
    if (i < M) {
        int excl = s[tid] - v + bpre;
        g_off[i] = excl;
        g_cursor[i] = excl;
        if (i == M - 1) g_off[M] = excl + v;
    }
}
__global__ void fill_csr(const void* ei, long E) {
    long e = (long)blockIdx.x * blockDim.x + threadIdx.x;
    if (e < E) {
        int row = (int)fetch_idx(ei, e);
        int col = (int)fetch_idx(ei, E + e);
        g_src[atomicAdd(&g_cursor[col], 1)] = row;
    }
}

// ---------------------------------------------------------------------------
// CSR aggregation fp8 -> fp16 (HFMA2). One warp per node.
// ---------------------------------------------------------------------------
__device__ __forceinline__ void q8h_fma(uint2 v, __half2 nm, __half2* acc) {
    acc[0] = __hfma2(fp8x2_to_h2((uint16_t)(v.x & 0xFFFF)), nm, acc[0]);
    acc[1] = __hfma2(fp8x2_to_h2((uint16_t)(v.x >> 16)),    nm, acc[1]);
    acc[2] = __hfma2(fp8x2_to_h2((uint16_t)(v.y & 0xFFFF)), nm, acc[2]);
    acc[3] = __hfma2(fp8x2_to_h2((uint16_t)(v.y >> 16)),    nm, acc[3]);
}

__global__ void __launch_bounds__(256, 8) agg_kernel(int M) {
    long gt = (long)blockIdx.x * blockDim.x + threadIdx.x;
    int n = (int)(gt >> 5);
    int lane = (int)(gt & 31);
    if (n >= M) return;

    const uint2* H8 = (const uint2*)g_H8;
    float dn = g_dinv[n];
    __half2 acc[4];
    acc[0] = acc[1] = acc[2] = acc[3] = __float2half2_rn(0.f);

    q8h_fma(__ldg(H8 + (long)n * 32 + lane), __float2half2_rn(dn * dn), acc);

    int i = g_off[n];
    int end = g_off[n + 1];

    for (; i + 3 < end; i += 4) {
        int r0 = __ldg(g_src + i + 0);
        int r1 = __ldg(g_src + i + 1);
        int r2 = __ldg(g_src + i + 2);
        int r3 = __ldg(g_src + i + 3);
        __half2 nm0 = __float2half2_rn(dn * __ldg(g_dinv + r0));
        __half2 nm1 = __float2half2_rn(dn * __ldg(g_dinv + r1));
        __half2 nm2 = __float2half2_rn(dn * __ldg(g_dinv + r2));
        __half2 nm3 = __float2half2_rn(dn * __ldg(g_dinv + r3));
        uint2 v0 = __ldg(H8 + (long)r0 * 32 + lane);
        uint2 v1 = __ldg(H8 + (long)r1 * 32 + lane);
        uint2 v2 = __ldg(H8 + (long)r2 * 32 + lane);
        uint2 v3 = __ldg(H8 + (long)r3 * 32 + lane);
        q8h_fma(v0, nm0, acc);
        q8h_fma(v1, nm1, acc);
        q8h_fma(v2, nm2, acc);
        q8h_fma(v3, nm3, acc);
    }
    for (; i < end; i++) {
        int r0 = __ldg(g_src + i);
        q8h_fma(__ldg(H8 + (long)r0 * 32 + lane),
                __float2half2_rn(dn * __ldg(g_dinv + r0)), acc);
    }

    uint4 o;
    o.x = *(uint32_t*)&acc[0];
    o.y = *(uint32_t*)&acc[1];
    o.z = *(uint32_t*)&acc[2];
    o.w = *(uint32_t*)&acc[3];
    ((uint4*)g_AGG16)[(long)n * 32 + lane] = o;
}

// ---------------------------------------------------------------------------
// Weight prep: both matrices in one launch
// ---------------------------------------------------------------------------
__global__ void prep_weights2(const float* __restrict__ Wa, const float* __restrict__ Wb,
                              uint32_t* __restrict__ img_a, uint32_t* __restrict__ img_b) {
    int idx = blockIdx.x * blockDim.x + threadIdx.x;
    const float* W = (idx < 32768) ? Wa : Wb;
    uint32_t* img = (idx < 32768) ? img_a : img_b;
    int li = idx & 32767;
    int tile = li >> 14;
    int k = (li >> 6) & 255;
    int np = li & 63;
    int n = np * 2;
    int gn = tile * 128 + n;
    float a = W[gn * 256 + k];
    float b = W[(gn + 1) * 256 + k];
    uint32_t boff = (uint32_t)k * 256 + ((((n >> 3) ^ (k & 7)) << 4) | ((n & 7) * 2));
    img[tile * 16384 + (boff >> 2)] = pack_bf16(a, b);
}

// ---------------------------------------------------------------------------
// HMMA GEMM, single-pass bf16, persistent blocks. grid (74, 2).
// smem: B 64KB | A 16KB.  OUT8: fp8 output. IN16: fp16 A. FUSED: W2 dot.
// ---------------------------------------------------------------------------
#define SM_B 0
#define SM_A 65536
#define SM_TOT 81920

template <bool PRE, bool POST, bool IN16, bool OUT8, bool FUSED>
__global__ void __launch_bounds__(256, 1)
gemm_hmma(const void* __restrict__ Avoid,
          const uint32_t* __restrict__ img,
          const float* __restrict__ bpre, const float* __restrict__ bpost,
          uint16_t* __restrict__ Out8, const float* __restrict__ W2,
          float* __restrict__ dotp, int M, int ntiles) {
    extern __shared__ char smem[];
    const uint32_t sb = smem_u32(smem);
    const int tid = threadIdx.x;
    const int lane = tid & 31;
    const int wid = tid >> 5;
    const int wm = wid & 3;
    const int wn = wid >> 2;
    const int n0 = blockIdx.y * 128;

    const float* Af = (const float*)Avoid;
    const __half* Ah16 = (const __half*)Avoid;

    // ---- copy B image ----
    {
        const uint4* sh = (const uint4*)(img + blockIdx.y * 16384);
        uint4* dh = (uint4*)(smem + SM_B);
#pragma unroll
        for (int i = 0; i < 16; i++)
            dh[tid + i * 256] = sh[tid + i * 256];
    }

    const int frow = tid >> 1;
    const int fkh = (tid & 1) * 32;

    float4 pf[8];
    uint4 pf16[4];
    int t = blockIdx.x;
    {
        bool ok = (t < ntiles) && (t * 128 + frow < M);
        if (IN16) {
            const uint4* Ab = (const uint4*)(Ah16 + (long)(t * 128 + frow) * 256 + fkh);
#pragma unroll
            for (int j = 0; j < 4; j++)
                pf16[j] = ok ? Ab[j] : make_uint4(0, 0, 0, 0);
        } else {
            const float* Ab = Af + (long)(t * 128 + frow) * 256 + fkh;
#pragma unroll
            for (int j = 0; j < 8; j++)
                pf[j] = ok ? *(const float4*)(Ab + j * 4) : make_float4(0.f, 0.f, 0.f, 0.f);
        }
    }

    const int g = lane >> 3;

    for (; t < ntiles; t += 74) {
        const int m0 = t * 128;
        float acc[2][8][4];
#pragma unroll
        for (int a_ = 0; a_ < 2; a_++)
#pragma unroll
            for (int b_ = 0; b_ < 8; b_++)
#pragma unroll
                for (int c_ = 0; c_ < 4; c_++) acc[a_][b_][c_] = 0.f;

        for (int ch = 0; ch < 4; ch++) {
            // ---- convert prefetched chunk -> A smem (bf16, swizzled) ----
            {
                uint32_t base_a = sb + SM_A + frow * 128;
                if (IN16) {
#pragma unroll
                    for (int j = 0; j < 4; j++) {
                        uint4 q = pf16[j];
                        float2 f0 = __half22float2(*(const __half2*)&q.x);
                        float2 f1 = __half22float2(*(const __half2*)&q.y);
                        float2 f2 = __half22float2(*(const __half2*)&q.z);
                        float2 f3 = __half22float2(*(const __half2*)&q.w);
                        if (PRE) {
                            const float4 b0 = *(const float4*)(bpre + ch * 64 + fkh + j * 8);
                            const float4 b1 = *(const float4*)(bpre + ch * 64 + fkh + j * 8 + 4);
                            f0.x = fmaxf(f0.x + b0.x, 0.f); f0.y = fmaxf(f0.y + b0.y, 0.f);
                            f1.x = fmaxf(f1.x + b0.z, 0.f); f1.y = fmaxf(f1.y + b0.w, 0.f);
                            f2.x = fmaxf(f2.x + b1.x, 0.f); f2.y = fmaxf(f2.y + b1.y, 0.f);
                            f3.x = fmaxf(f3.x + b1.z, 0.f); f3.y = fmaxf(f3.y + b1.w, 0.f);
                        }
                        uint32_t h0 = pack_bf16(f0.x, f0.y);
                        uint32_t h1 = pack_bf16(f1.x, f1.y);
                        uint32_t h2 = pack_bf16(f2.x, f2.y);
                        uint32_t h3 = pack_bf16(f3.x, f3.y);
                        int kk = fkh + j * 8;
                        uint32_t off0 = ((((kk >> 3) ^ (frow & 7)) << 4));
                        asm volatile("st.shared.v2.b32 [%0], {%1, %2};"
                                     :: "r"(base_a + off0), "r"(h0), "r"(h1) : "memory");
                        asm volatile("st.shared.v2.b32 [%0], {%1, %2};"
                                     :: "r"(base_a + off0 + 8), "r"(h2), "r"(h3) : "memory");
                    }
                } else {
#pragma unroll
                    for (int j = 0; j < 8; j++) {
                        float4 v = pf[j];
                        if (PRE) {
                            const float4 bb = *(const float4*)(bpre + ch * 64 + fkh + j * 4);
                            v.x = fmaxf(v.x + bb.x, 0.f);
                            v.y = fmaxf(v.y + bb.y, 0.f);
                            v.z = fmaxf(v.z + bb.z, 0.f);
                            v.w = fmaxf(v.w + bb.w, 0.f);
                        }
                        uint32_t h0 = pack_bf16(v.x, v.y);
                        uint32_t h1 = pack_bf16(v.z, v.w);
                        int kk = fkh + j * 4;
                        uint32_t off = ((((kk >> 3) ^ (frow & 7)) << 4) | ((kk & 7) * 2));
                        asm volatile("st.shared.v2.b32 [%0], {%1, %2};"
                                     :: "r"(base_a + off), "r"(h0), "r"(h1) : "memory");
                    }
                }
            }
            __syncthreads();

            // ---- prefetch next chunk ----
            {
                int nc = ch + 1;
                int nt = t;
                if (nc == 4) { nc = 0; nt = t + 74; }
                if (nt < ntiles) {
                    bool ok = (nt * 128 + frow) < M;
                    if (IN16) {
                        const uint4* Ab = (const uint4*)(Ah16 + (long)(nt * 128 + frow) * 256 + nc * 64 + fkh);
#pragma unroll
                        for (int j = 0; j < 4; j++)
                            pf16[j] = ok ? Ab[j] : make_uint4(0, 0, 0, 0);
                    } else {
                        const float* Ab = Af + (long)(nt * 128 + frow) * 256 + nc * 64 + fkh;
#pragma unroll
                        for (int j = 0; j < 8; j++)
                            pf[j] = ok ? *(const float4*)(Ab + j * 4) : make_float4(0.f, 0.f, 0.f, 0.f);
                    }
                }
            }

            // ---- MMA over 4 k16 steps ----
#pragma unroll
            for (int ks = 0; ks < 4; ks++) {
                const int klocal = ks * 16;
                const int kglob = ch * 64 + klocal;

                uint32_t ah[2][4];
#pragma unroll
                for (int mf = 0; mf < 2; mf++) {
                    int m = wm * 32 + mf * 16 + ((g & 1) << 3) + (lane & 7);
                    int kc = klocal + ((g >> 1) << 3);
                    uint32_t off = (uint32_t)m * 128 + ((((kc >> 3) ^ (m & 7)) << 4));
                    ldsm_x4(ah[mf], sb + SM_A + off);
                }

                uint32_t bh[8][2];
#pragma unroll
                for (int q = 0; q < 4; q++) {
                    int nb = wn * 64 + q * 16 + ((g >> 1) << 3);
                    int kr = kglob + ((g & 1) << 3) + (lane & 7);
                    uint32_t off = (uint32_t)kr * 256 + ((((nb >> 3) ^ (kr & 7)) << 4));
                    uint32_t r[4];
                    ldsm_x4_t(r, sb + SM_B + off);
                    bh[q * 2][0] = r[0]; bh[q * 2][1] = r[1];
                    bh[q * 2 + 1][0] = r[2]; bh[q * 2 + 1][1] = r[3];
                }

#pragma unroll
                for (int mf = 0; mf < 2; mf++)
#pragma unroll
                    for (int nf = 0; nf < 8; nf++)
                        mma_bf16(acc[mf][nf], ah[mf], bh[nf]);
            }
            __syncthreads();
        }

        // ---- epilogue ----
#pragma unroll
        for (int mf = 0; mf < 2; mf++) {
#pragma unroll
            for (int half = 0; half < 2; half++) {
                int m = m0 + wm * 32 + mf * 16 + (lane >> 2) + half * 8;
                float dot = 0.f;
#pragma unroll
                for (int nf = 0; nf < 8; nf++) {
                    float2 v;
                    v.x = acc[mf][nf][half * 2];
                    v.y = acc[mf][nf][half * 2 + 1];
                    if (POST) {
                        const float2 bb = *(const float2*)(bpost + n0 + wn * 64 + nf * 8 + 2 * (lane & 3));
                        v.x = fmaxf(v.x + bb.x, 0.f);
                        v.y = fmaxf(v.y + bb.y, 0.f);
                    }
                    if (FUSED) {
                        const float2 w2v = *(const float2*)(W2 + n0 + wn * 64 + nf * 8 + 2 * (lane & 3));
                        dot = fmaf(v.x, w2v.x, dot);
                        dot = fmaf(v.y, w2v.y, dot);
                    } else if (OUT8) {
                        if (m < M) {
                            int col = n0 + wn * 64 + nf * 8 + 2 * (lane & 3);
                            Out8[(long)m * 128 + (col >> 1)] = pack_fp8x2(v.x, v.y);
                        }
                    }
                }
                if (FUSED) {
                    dot += __shfl_xor_sync(0xFFFFFFFFu, dot, 1);
                    dot += __shfl_xor_sync(0xFFFFFFFFu, dot, 2);
                    if ((lane & 3) == 0 && m < M)
                        dotp[(long)m * 4 + blockIdx.y * 2 + wn] = dot;
                }
            }
        }
    }
}

// ---------------------------------------------------------------------------
// Final combine
// ---------------------------------------------------------------------------
__global__ void final_combine(const float* __restrict__ b2, float* __restrict__ out, int M) {
    int m = blockIdx.x * blockDim.x + threadIdx.x;
    if (m < M) {
        float4 p = ((const float4*)g_dotp)[m];
        float v = fmaxf(p.x + p.y + p.z + p.w + b2[0], 0.f);
        out[m] = 1.f / (1.f + __expf(-v));
    }
}

// ---------------------------------------------------------------------------
extern "C" void kernel_launch(void* const* d_in, const int* in_sizes, int n_in,
                              void* d_out, int out_size) {
    const float* x     = (const float*)d_in[0];
    const void*  ei    = d_in[1];
    const float* W_gcn = (const float*)d_in[2];
    const float* b_gcn = (const float*)d_in[3];
    const float* W1    = (const float*)d_in[4];
    const float* b1    = (const float*)d_in[5];
    const float* W2    = (const float*)d_in[6];
    const float* b2    = (const float*)d_in[7];
    float* out = (float*)d_out;

    const int  M = in_sizes[0] / C;
    const long E = (long)in_sizes[1] / 2;
    const int ntiles = (M + 127) / 128;

    uint16_t* H8;
    __half* AGG16;
    float* dotp;
    cudaGetSymbolAddress((void**)&H8, g_H8);
    cudaGetSymbolAddress((void**)&AGG16, g_AGG16);
    cudaGetSymbolAddress((void**)&dotp, g_dotp);
    uint32_t *W0, *W1i;
    cudaGetSymbolAddress((void**)&W0, g_W0);
    cudaGetSymbolAddress((void**)&W1i, g_W1);

    static cudaStream_t s1 = nullptr;
    static cudaEvent_t evFork = nullptr, evJoin = nullptr;
    if (!s1) {
        cudaStreamCreateWithFlags(&s1, cudaStreamNonBlocking);
        cudaEventCreateWithFlags(&evFork, cudaEventDisableTiming);
        cudaEventCreateWithFlags(&evJoin, cudaEventDisableTiming);
        cudaFuncSetAttribute(gemm_hmma<false, false, false, true, false>,
                             cudaFuncAttributeMaxDynamicSharedMemorySize, SM_TOT);
        cudaFuncSetAttribute(gemm_hmma<true, true, true, false, true>,
                             cudaFuncAttributeMaxDynamicSharedMemorySize, SM_TOT);
    }

    // ---- fork: stream 0 = CSR chain, s1 = weights + GEMM1 ----
    cudaEventRecord(evFork, 0);
    cudaStreamWaitEvent(s1, evFork, 0);

    // chain A (stream 0): init(detect+zero) -> count -> scan1(+dinv) -> scan3(merged) -> fill
    init_kernel<<<(M + 255) / 256, 256>>>(ei, E, M);
    count_deg<<<(int)((E + 255) / 256), 256>>>(ei, E);
    int nb = (M + 1023) / 1024;
    scan_phase1<<<nb, 1024>>>(M);
    scan_phase3<<<nb, 1024>>>(M);
    fill_csr<<<(int)((E + 255) / 256), 256>>>(ei, E);

    // chain B (s1): weight prep (both) + GEMM1 (H8 = fp8(x @ W_gcn^T))
    prep_weights2<<<256, 256, 0, s1>>>(W_gcn, W1, W0, W1i);
    dim3 ggrid(74, 2);
    gemm_hmma<false, false, false, true, false><<<ggrid, 256, SM_TOT, s1>>>(
        x, W0, nullptr, nullptr, H8, nullptr, nullptr, M, ntiles);

    // ---- join ----
    cudaEventRecord(evJoin, s1);
    cudaStreamWaitEvent(0, evJoin, 0);

    // agg: fp8 gather, HFMA2 half2 accumulate, fp16 store
    {
        long tcount = (long)M * 32;
        agg_kernel<<<(int)((tcount + 255) / 256), 256>>>(M);
    }

    // GEMM2 fused: partial dots of relu(relu(AGG+b_gcn)@W1^T + b1) with W2
    gemm_hmma<true, true, true, false, true><<<ggrid, 256, SM_TOT>>>(
        AGG16, W1i, b_gcn, b1, nullptr, W2, dotp, M, ntiles);

    // combine + sigmoid
    final_combine<<<(M + 255) / 256, 256>>>(b2, out, M);
}